// round 1
// baseline (speedup 1.0000x reference)
#include <cuda_runtime.h>
#include <math.h>

// Problem constants
#define NB 4
#define NS 2048
#define ND 1024
#define NH 16
#define HD 64
#define NM (NB*NS)          // 8192 rows

// ---------------- scratch (device globals: no allocation allowed) ----------
__device__ float g_q[(size_t)NM*ND];
__device__ float g_k[(size_t)NM*ND];
__device__ float g_v[(size_t)NM*ND];
__device__ float g_o[(size_t)NM*ND];
__device__ float g_sin[NS*(HD/2)];
__device__ float g_cos[NS*(HD/2)];

// ---------------- trig tables (double precision, tiny) ---------------------
__global__ void trig_kernel() {
    int i = blockIdx.x*blockDim.x + threadIdx.x;
    if (i >= NS*(HD/2)) return;
    int pos = i >> 5;           // 0..2047
    int j   = i & 31;           // pair index within head (hd/2 = 32)
    double angle = exp(-((double)j/31.0)*log(10000.0));
    double arg = (double)pos * angle;
    g_sin[i] = (float)sin(arg);
    g_cos[i] = (float)cos(arg);
}

// ---------------- SGEMM: C[M,N] = A[M,K] @ B[N,K]^T  (both K-major) --------
#define BM 128
#define BN 128
#define BK 16

__global__ __launch_bounds__(256)
void sgemm_nt(const float* __restrict__ A, const float* __restrict__ B,
              float* __restrict__ C, int M, int N, int K) {
    __shared__ float As[BK][BM+4];   // transposed tiles [k][m], pad 4 -> stride 132
    __shared__ float Bs[BK][BN+4];
    int tid = threadIdx.x;
    int tx = tid & 15, ty = tid >> 4;
    int m0 = blockIdx.y * BM, n0 = blockIdx.x * BN;
    const float* Ab = A + (size_t)m0 * K;
    const float* Bb = B + (size_t)n0 * K;
    float acc[8][8] = {};
    for (int k0 = 0; k0 < K; k0 += BK) {
#pragma unroll
        for (int i = 0; i < 2; i++) {
            int idx = tid + i*256;          // 0..511
            int row = idx >> 2;             // 0..127
            int c4  = (idx & 3) << 2;       // 0,4,8,12
            float4 va = *(const float4*)(Ab + (size_t)row*K + k0 + c4);
            As[c4+0][row]=va.x; As[c4+1][row]=va.y; As[c4+2][row]=va.z; As[c4+3][row]=va.w;
            float4 vb = *(const float4*)(Bb + (size_t)row*K + k0 + c4);
            Bs[c4+0][row]=vb.x; Bs[c4+1][row]=vb.y; Bs[c4+2][row]=vb.z; Bs[c4+3][row]=vb.w;
        }
        __syncthreads();
#pragma unroll
        for (int k = 0; k < BK; k++) {
            float a[8], b[8];
            *(float4*)&a[0] = *(const float4*)&As[k][ty*8];
            *(float4*)&a[4] = *(const float4*)&As[k][ty*8+4];
            *(float4*)&b[0] = *(const float4*)&Bs[k][tx*8];
            *(float4*)&b[4] = *(const float4*)&Bs[k][tx*8+4];
#pragma unroll
            for (int i = 0; i < 8; i++)
#pragma unroll
                for (int j = 0; j < 8; j++)
                    acc[i][j] = fmaf(a[i], b[j], acc[i][j]);
        }
        __syncthreads();
    }
#pragma unroll
    for (int i = 0; i < 8; i++) {
#pragma unroll
        for (int j = 0; j < 8; j += 4) {
            float4 v = make_float4(acc[i][j],acc[i][j+1],acc[i][j+2],acc[i][j+3]);
            *(float4*)(C + (size_t)(m0+ty*8+i)*N + n0 + tx*8 + j) = v;
        }
    }
}

// ---------------- RoPE (in-place on g_q, g_k) -------------------------------
__global__ void rope_kernel() {
    int i = blockIdx.x*blockDim.x + threadIdx.x;   // over NM*512 pairs
    if (i >= NM*(ND/2)) return;
    int m = i >> 9;                 // row
    int p = i & 511;                // pair index within 1024 feats
    int pos = m & (NS-1);
    int j = p & 31;                 // pair within head
    float s = g_sin[pos*32 + j];
    float c = g_cos[pos*32 + j];
    float2* qp = (float2*)g_q;
    float2* kp = (float2*)g_k;
    float2 v = qp[i];
    qp[i] = make_float2(v.x*c - v.y*s, v.y*c + v.x*s);
    float2 w = kp[i];
    kp[i] = make_float2(w.x*c - w.y*s, w.y*c + w.x*s);
}

// ---------------- attention: causal decay-masked, per (b,h) ----------------
// grid: (qblk 0..31, h 0..15, b 0..3), 256 threads, dynamic smem.
// Layout (floats): Qs[64][64] | Ks[64][65] | Vs[64][64] | St[64][65]
#define ATTN_SMEM_FLOATS (64*64 + 64*65 + 64*64 + 64*65)
#define ATTN_SMEM_BYTES  (ATTN_SMEM_FLOATS*4)

__global__ __launch_bounds__(256)
void attn_kernel() {
    extern __shared__ float sm[];
    float* Qs = sm;              // [qr][e]  stride 64
    float* Ks = Qs + 64*64;      // [t][e]   stride 65 (pad for bank spread)
    float* Vs = Ks + 64*65;      // [t][e]   stride 64 (float4 friendly)
    float* St = Vs + 64*64;      // [t][qr]  stride 65

    int qblk = blockIdx.x, h = blockIdx.y, bb = blockIdx.z;
    int tid = threadIdx.x;
    int tx = tid & 15, ty = tid >> 4;
    size_t base = ((size_t)bb*NS)*ND + (size_t)h*HD;
    int q0 = qblk * 64;

    float dec = (float)log(1.0 - exp2(-5.0 - (double)h));   // negative

    // load Q tile [64 rows][64 feats]
#pragma unroll
    for (int i = 0; i < 4; i++) {
        int idx = tid + i*256;
        int row = idx >> 4;
        int c4  = (idx & 15) << 2;
        float4 v = *(const float4*)(g_q + base + (size_t)(q0+row)*ND + c4);
        *(float4*)&Qs[row*64 + c4] = v;
    }

    float oacc[4][4] = {};
    int ntiles = qblk + 1;
    for (int tt = 0; tt < ntiles; tt++) {
        int t0 = tt * 64;
        __syncthreads();   // prev O-gemm done reading Vs/St; Q load done (1st iter)
#pragma unroll
        for (int i = 0; i < 4; i++) {
            int idx = tid + i*256;
            int row = idx >> 4;
            int c4  = (idx & 15) << 2;
            float4 vk = *(const float4*)(g_k + base + (size_t)(t0+row)*ND + c4);
            Ks[row*65 + c4+0]=vk.x; Ks[row*65 + c4+1]=vk.y;
            Ks[row*65 + c4+2]=vk.z; Ks[row*65 + c4+3]=vk.w;
            float4 vv = *(const float4*)(g_v + base + (size_t)(t0+row)*ND + c4);
            *(float4*)&Vs[row*64 + c4] = vv;
        }
        __syncthreads();

        // S = Q K^T  (64x64x64)
        float s[4][4] = {};
#pragma unroll 8
        for (int e = 0; e < 64; e++) {
            float a[4], b[4];
#pragma unroll
            for (int i = 0; i < 4; i++) a[i] = Qs[(ty*4+i)*64 + e];
#pragma unroll
            for (int j = 0; j < 4; j++) b[j] = Ks[(tx*4+j)*65 + e];
#pragma unroll
            for (int i = 0; i < 4; i++)
#pragma unroll
                for (int j = 0; j < 4; j++)
                    s[i][j] = fmaf(a[i], b[j], s[i][j]);
        }

        // decay mask: exp(dec*(gq-gt)) for gq>=gt else 0, factored per tile
        float rowf[4], colf[4];
#pragma unroll
        for (int i = 0; i < 4; i++) rowf[i] = __expf(dec * (float)(q0 + ty*4+i - t0));
#pragma unroll
        for (int j = 0; j < 4; j++) colf[j] = __expf(-dec * (float)(tx*4+j));
        bool diag = (tt == qblk);
#pragma unroll
        for (int i = 0; i < 4; i++)
#pragma unroll
            for (int j = 0; j < 4; j++) {
                float mval = rowf[i]*colf[j];
                if (diag && (tx*4+j > ty*4+i)) mval = 0.f;
                s[i][j] *= mval;
            }

        // store S transposed: St[t][qr]
#pragma unroll
        for (int i = 0; i < 4; i++)
#pragma unroll
            for (int j = 0; j < 4; j++)
                St[(tx*4+j)*65 + ty*4+i] = s[i][j];
        __syncthreads();

        // O += S @ V  (64x64x64)
#pragma unroll 8
        for (int t = 0; t < 64; t++) {
            float a[4];
#pragma unroll
            for (int i = 0; i < 4; i++) a[i] = St[t*65 + ty*4+i];
            float4 b4 = *(const float4*)&Vs[t*64 + tx*4];
            float b[4] = {b4.x, b4.y, b4.z, b4.w};
#pragma unroll
            for (int i = 0; i < 4; i++)
#pragma unroll
                for (int j = 0; j < 4; j++)
                    oacc[i][j] = fmaf(a[i], b[j], oacc[i][j]);
        }
    }
#pragma unroll
    for (int i = 0; i < 4; i++) {
        float4 v = make_float4(oacc[i][0],oacc[i][1],oacc[i][2],oacc[i][3]);
        *(float4*)(g_o + base + (size_t)(q0+ty*4+i)*ND + tx*4) = v;
    }
}

// ---------------- LayerNorm(hd=64) + SiLU, in-place on g_o ------------------
__global__ __launch_bounds__(256)
void ln_silu_kernel(const float* __restrict__ lnw, const float* __restrict__ lnb) {
    int warp = (blockIdx.x*blockDim.x + threadIdx.x) >> 5;  // one warp per group
    int lane = threadIdx.x & 31;
    if (warp >= NM*NH) return;
    float* p = g_o + (size_t)warp * HD;
    float2 v = ((float2*)p)[lane];
    float sum = v.x + v.y;
    float sq  = v.x*v.x + v.y*v.y;
#pragma unroll
    for (int o = 16; o > 0; o >>= 1) {
        sum += __shfl_xor_sync(0xffffffffu, sum, o);
        sq  += __shfl_xor_sync(0xffffffffu, sq, o);
    }
    float mean = sum * (1.f/64.f);
    float var  = sq * (1.f/64.f) - mean*mean;
    float rs = rsqrtf(var + 1e-5f);
    int e0 = lane*2;
    float y0 = (v.x - mean)*rs*lnw[e0]   + lnb[e0];
    float y1 = (v.y - mean)*rs*lnw[e0+1] + lnb[e0+1];
    y0 = y0 / (1.f + __expf(-y0));
    y1 = y1 / (1.f + __expf(-y1));
    ((float2*)p)[lane] = make_float2(y0, y1);
}

// ---------------- launcher ---------------------------------------------------
extern "C" void kernel_launch(void* const* d_in, const int* in_sizes, int n_in,
                              void* d_out, int out_size) {
    const float* x   = (const float*)d_in[0];
    const float* Wq  = (const float*)d_in[1];
    const float* Wk  = (const float*)d_in[2];
    const float* Wv  = (const float*)d_in[3];
    const float* Wo  = (const float*)d_in[4];
    const float* lnw = (const float*)d_in[5];
    const float* lnb = (const float*)d_in[6];
    float* out = (float*)d_out;

    float *q, *k, *v, *o;
    cudaGetSymbolAddress((void**)&q, g_q);
    cudaGetSymbolAddress((void**)&k, g_k);
    cudaGetSymbolAddress((void**)&v, g_v);
    cudaGetSymbolAddress((void**)&o, g_o);

    trig_kernel<<<(NS*(HD/2)+255)/256, 256>>>();

    dim3 ggrid(ND/BN, NM/BM);   // (8, 64)
    sgemm_nt<<<ggrid, 256>>>(x, Wq, q, NM, ND, ND);
    sgemm_nt<<<ggrid, 256>>>(x, Wk, k, NM, ND, ND);
    sgemm_nt<<<ggrid, 256>>>(x, Wv, v, NM, ND, ND);

    rope_kernel<<<(NM*(ND/2)+255)/256, 256>>>();

    cudaFuncSetAttribute(attn_kernel, cudaFuncAttributeMaxDynamicSharedMemorySize,
                         ATTN_SMEM_BYTES);
    attn_kernel<<<dim3(NS/64, NH, NB), 256, ATTN_SMEM_BYTES>>>();

    ln_silu_kernel<<<(NM*NH*32 + 255)/256, 256>>>(lnw, lnb);

    sgemm_nt<<<ggrid, 256>>>(o, Wo, out, NM, ND, ND);
}